// round 11
// baseline (speedup 1.0000x reference)
#include <cuda_runtime.h>
#include <cstdint>
#include <math_constants.h>

// Sparsemax (faithful-to-buggy-reference): per contiguous row of K=2048:
//   r = inclusive cumsum(z); unmasked_k: 1 + k*z_k > r_k (1-indexed)
//   kmax = max unmasked k; tmax = max unmasked r_k
//   tau = (tmax-1)/kmax; out = max(0, z - tau)
//
// R11: two independent rows per CTA of 128 threads (4 warps), 16 elems per
// row per thread (128*16 = 2048 = K). Versus R8 (256thr/EPT8): same ILP-2
// interleaved serial chains and 1 barrier/row, but the per-thread warp-scan
// cost per element HALVES (2 scans x 5 steps over 32 elems) and the tail
// combines run on half the threads per row-pair. R10's lesson applied:
// fewer instructions beats more interleave.

constexpr int K       = 2048;
constexpr int THREADS = 128;
constexpr int EPT     = 16;             // elems per row per thread
constexpr int NW      = THREADS / 32;   // 4 warps
constexpr int ROWF4   = K / 4;          // 512 float4 per row

static_assert(THREADS * EPT == K, "full row coverage");

__device__ __forceinline__ unsigned f2ord(float f) {
    unsigned u = __float_as_uint(f);
    return (u & 0x80000000u) ? ~u : (u | 0x80000000u);
}
__device__ __forceinline__ float ord2f(unsigned u) {
    return __uint_as_float((u & 0x80000000u) ? (u ^ 0x80000000u) : ~u);
}

__global__ __launch_bounds__(THREADS)
void sparsemax_rowwise_kernel(const float* __restrict__ x, float* __restrict__ y,
                              int nrows)
{
    const int tid  = threadIdx.x;
    const int lane = tid & 31;
    const int wid  = tid >> 5;
    const int rowA = blockIdx.x * 2;
    const bool hasB = (rowA + 1 < nrows);

    const float4* __restrict__ xa =
        reinterpret_cast<const float4*>(x) + (size_t)rowA * ROWF4 + tid * 4;
    const float4* __restrict__ xb = hasB ? (xa + ROWF4) : xa;

    // 8 independent LDG.128 in flight (default policy — input stays in L2)
    float4 a0 = xa[0], a1 = xa[1], a2 = xa[2], a3 = xa[3];
    float4 b0 = xb[0], b1 = xb[1], b2 = xb[2], b3 = xb[3];

    float zA[EPT] = {a0.x, a0.y, a0.z, a0.w, a1.x, a1.y, a1.z, a1.w,
                     a2.x, a2.y, a2.z, a2.w, a3.x, a3.y, a3.z, a3.w};
    float zB[EPT] = {b0.x, b0.y, b0.z, b0.w, b1.x, b1.y, b1.z, b1.w,
                     b2.x, b2.y, b2.z, b2.w, b3.x, b3.y, b3.z, b3.w};

    // Per-thread totals (pairwise trees, independent)
    float pA0 = (zA[0]  + zA[1])  + (zA[2]  + zA[3]);
    float pA1 = (zA[4]  + zA[5])  + (zA[6]  + zA[7]);
    float pA2 = (zA[8]  + zA[9])  + (zA[10] + zA[11]);
    float pA3 = (zA[12] + zA[13]) + (zA[14] + zA[15]);
    float pB0 = (zB[0]  + zB[1])  + (zB[2]  + zB[3]);
    float pB1 = (zB[4]  + zB[5])  + (zB[6]  + zB[7]);
    float pB2 = (zB[8]  + zB[9])  + (zB[10] + zB[11]);
    float pB3 = (zB[12] + zB[13]) + (zB[14] + zB[15]);
    const float totA = (pA0 + pA1) + (pA2 + pA3);
    const float totB = (pB0 + pB1) + (pB2 + pB3);

    // Two interleaved warp inclusive scans
    float scA = totA, scB = totB;
    #pragma unroll
    for (int o = 1; o < 32; o <<= 1) {
        float tA = __shfl_up_sync(0xffffffffu, scA, o);
        float tB = __shfl_up_sync(0xffffffffu, scB, o);
        if (lane >= o) { scA += tA; scB += tB; }
    }

    __shared__ float    wsum[2][NW];
    __shared__ unsigned wkt[4][NW];   // kA, kB, tA, tB

    if (lane == 31) { wsum[0][wid] = scA; wsum[1][wid] = scB; }
    __syncthreads();

    // Lane-parallel cross-warp exclusive offsets: 4-lane shuffle scan
    {
        const int g = lane & 3;
        float vA = wsum[0][g];
        float vB = wsum[1][g];
        #pragma unroll
        for (int o = 1; o < NW; o <<= 1) {
            float tA = __shfl_up_sync(0xffffffffu, vA, o);
            float tB = __shfl_up_sync(0xffffffffu, vB, o);
            if (g >= o) { vA += tA; vB += tB; }
        }
        float incA = __shfl_sync(0xffffffffu, vA, wid);
        float incB = __shfl_sync(0xffffffffu, vB, wid);
        scA += incA - wsum[0][wid] - totA;   // exclusive base for element 0
        scB += incB - wsum[1][wid] - totB;
    }

    // Running prefix + mask maxes (ILP-2 interleaved)
    float runA = scA, runB = scB;
    const float kb = (float)(tid * EPT);
    float kmaxA = 0.0f, kmaxB = 0.0f;
    float tmaxA = -CUDART_INF_F, tmaxB = -CUDART_INF_F;
    #pragma unroll
    for (int e = 0; e < EPT; e++) {
        const float kk = kb + (float)(e + 1);
        runA += zA[e];
        runB += zB[e];
        if (fmaf(kk, zA[e], 1.0f) > runA) {
            kmaxA = fmaxf(kmaxA, kk);
            tmaxA = fmaxf(tmaxA, runA);
        }
        if (fmaf(kk, zB[e], 1.0f) > runB) {
            kmaxB = fmaxf(kmaxB, kk);
            tmaxB = fmaxf(tmaxB, runB);
        }
    }

    // Warp-level REDUX, then lane-parallel cross-warp REDUX
    unsigned kuA = __reduce_max_sync(0xffffffffu, __float2uint_rz(kmaxA));
    unsigned kuB = __reduce_max_sync(0xffffffffu, __float2uint_rz(kmaxB));
    unsigned tuA = __reduce_max_sync(0xffffffffu, f2ord(tmaxA));
    unsigned tuB = __reduce_max_sync(0xffffffffu, f2ord(tmaxB));

    if (lane == 0) {
        wkt[0][wid] = kuA; wkt[1][wid] = kuB;
        wkt[2][wid] = tuA; wkt[3][wid] = tuB;
    }
    __syncthreads();

    // Masked full-warp REDUX over 4 per-warp values (identity 0 safe:
    // f2ord values are > 0, kmax counts >= 1).
    const bool in4 = (lane < NW);
    unsigned kmA = __reduce_max_sync(0xffffffffu, in4 ? wkt[0][lane] : 0u);
    unsigned kmB = __reduce_max_sync(0xffffffffu, in4 ? wkt[1][lane] : 0u);
    unsigned tmA = __reduce_max_sync(0xffffffffu, in4 ? wkt[2][lane] : 0u);
    unsigned tmB = __reduce_max_sync(0xffffffffu, in4 ? wkt[3][lane] : 0u);

    const float tauA = __fdividef(ord2f(tmA) - 1.0f, __uint2float_rn(kmA));
    const float tauB = __fdividef(ord2f(tmB) - 1.0f, __uint2float_rn(kmB));

    // Outputs (streaming stores — output evicts first, input keeps L2)
    float4* __restrict__ ya =
        reinterpret_cast<float4*>(y) + (size_t)rowA * ROWF4 + tid * 4;
    #pragma unroll
    for (int j = 0; j < 4; j++) {
        float4 o;
        o.x = fmaxf(0.0f, zA[j * 4 + 0] - tauA);
        o.y = fmaxf(0.0f, zA[j * 4 + 1] - tauA);
        o.z = fmaxf(0.0f, zA[j * 4 + 2] - tauA);
        o.w = fmaxf(0.0f, zA[j * 4 + 3] - tauA);
        __stcs(ya + j, o);
    }
    if (hasB) {
        float4* __restrict__ yb = ya + ROWF4;
        #pragma unroll
        for (int j = 0; j < 4; j++) {
            float4 o;
            o.x = fmaxf(0.0f, zB[j * 4 + 0] - tauB);
            o.y = fmaxf(0.0f, zB[j * 4 + 1] - tauB);
            o.z = fmaxf(0.0f, zB[j * 4 + 2] - tauB);
            o.w = fmaxf(0.0f, zB[j * 4 + 3] - tauB);
            __stcs(yb + j, o);
        }
    }
}

extern "C" void kernel_launch(void* const* d_in, const int* in_sizes, int n_in,
                              void* d_out, int out_size)
{
    const float* x = (const float*)d_in[0];
    float*       y = (float*)d_out;
    const int rows = out_size / K;             // 8192 for the bench shape
    const int grid = (rows + 1) / 2;           // 4096
    sparsemax_rowwise_kernel<<<grid, THREADS>>>(x, y, rows);
}

// round 12
// speedup vs baseline: 1.1554x; 1.1554x over previous
#include <cuda_runtime.h>
#include <cstdint>
#include <math_constants.h>

// Sparsemax (faithful-to-buggy-reference): per contiguous row of K=2048:
//   r = inclusive cumsum(z); unmasked_k: 1 + k*z_k > r_k (1-indexed)
//   kmax = max unmasked k; tmax = max unmasked r_k
//   tau = (tmax-1)/kmax; out = max(0, z - tau)
//
// R12 = R8 (the 26.9us optimum: two rows per 256-thread CTA, ILP-2
// interleaved chains, lane-parallel tail combines, default-policy loads +
// __stcs stores) with __launch_bounds__(256, 7): pins regs <= 36 so 7 CTAs
// (56 warps) fit per SM instead of 6, converting R8's register slack into
// latency-hiding warps at zero instruction cost.

constexpr int K       = 2048;
constexpr int THREADS = 256;
constexpr int EPT     = 8;              // elems per row per thread
constexpr int NW      = THREADS / 32;   // 8 warps
constexpr int ROWF4   = K / 4;          // 512 float4 per row

static_assert(THREADS * EPT == K, "full row coverage");

__device__ __forceinline__ unsigned f2ord(float f) {
    unsigned u = __float_as_uint(f);
    return (u & 0x80000000u) ? ~u : (u | 0x80000000u);
}
__device__ __forceinline__ float ord2f(unsigned u) {
    return __uint_as_float((u & 0x80000000u) ? (u ^ 0x80000000u) : ~u);
}

__global__ __launch_bounds__(THREADS, 7)
void sparsemax_rowwise_kernel(const float* __restrict__ x, float* __restrict__ y,
                              int nrows)
{
    const int tid  = threadIdx.x;
    const int lane = tid & 31;
    const int wid  = tid >> 5;
    const int rowA = blockIdx.x * 2;
    const bool hasB = (rowA + 1 < nrows);

    const float4* __restrict__ xa =
        reinterpret_cast<const float4*>(x) + (size_t)rowA * ROWF4 + tid * 2;
    const float4* __restrict__ xb = hasB ? (xa + ROWF4) : xa;

    // 8 independent LDG.128 in flight, default cache policy (L2-friendly)
    float4 a0 = xa[0];
    float4 a1 = xa[1];
    float4 b0 = xb[0];
    float4 b1 = xb[1];

    float zA[EPT] = {a0.x, a0.y, a0.z, a0.w, a1.x, a1.y, a1.z, a1.w};
    float zB[EPT] = {b0.x, b0.y, b0.z, b0.w, b1.x, b1.y, b1.z, b1.w};

    // Per-thread totals (independent pairwise trees)
    const float totA = ((zA[0] + zA[1]) + (zA[2] + zA[3]))
                     + ((zA[4] + zA[5]) + (zA[6] + zA[7]));
    const float totB = ((zB[0] + zB[1]) + (zB[2] + zB[3]))
                     + ((zB[4] + zB[5]) + (zB[6] + zB[7]));

    // Two interleaved warp inclusive scans
    float scA = totA, scB = totB;
    #pragma unroll
    for (int o = 1; o < 32; o <<= 1) {
        float tA = __shfl_up_sync(0xffffffffu, scA, o);
        float tB = __shfl_up_sync(0xffffffffu, scB, o);
        if (lane >= o) { scA += tA; scB += tB; }
    }

    __shared__ float    wsum[2][NW];
    __shared__ unsigned wkt[4][NW];   // kA, kB, tA, tB

    if (lane == 31) { wsum[0][wid] = scA; wsum[1][wid] = scB; }
    __syncthreads();

    // Lane-parallel cross-warp exclusive offsets: 8-lane shuffle scan.
    {
        const int g = lane & 7;
        float vA = wsum[0][g];
        float vB = wsum[1][g];
        #pragma unroll
        for (int o = 1; o < NW; o <<= 1) {
            float tA = __shfl_up_sync(0xffffffffu, vA, o);
            float tB = __shfl_up_sync(0xffffffffu, vB, o);
            if (g >= o) { vA += tA; vB += tB; }
        }
        // inclusive prefix for this thread's warp, minus own warp sum
        float incA = __shfl_sync(0xffffffffu, vA, wid);
        float incB = __shfl_sync(0xffffffffu, vB, wid);
        scA += incA - wsum[0][wid] - totA;   // exclusive base for element 0
        scB += incB - wsum[1][wid] - totB;
    }

    // Running prefix + mask maxes (interleaved, independent)
    float runA = scA, runB = scB;
    const float kb = (float)(tid * EPT);
    float kmaxA = 0.0f, kmaxB = 0.0f;
    float tmaxA = -CUDART_INF_F, tmaxB = -CUDART_INF_F;
    #pragma unroll
    for (int e = 0; e < EPT; e++) {
        const float kk = kb + (float)(e + 1);
        runA += zA[e];
        runB += zB[e];
        if (fmaf(kk, zA[e], 1.0f) > runA) {
            kmaxA = fmaxf(kmaxA, kk);
            tmaxA = fmaxf(tmaxA, runA);
        }
        if (fmaf(kk, zB[e], 1.0f) > runB) {
            kmaxB = fmaxf(kmaxB, kk);
            tmaxB = fmaxf(tmaxB, runB);
        }
    }

    // Warp-level REDUX, then lane-parallel cross-warp REDUX
    unsigned kuA = __reduce_max_sync(0xffffffffu, __float2uint_rz(kmaxA));
    unsigned kuB = __reduce_max_sync(0xffffffffu, __float2uint_rz(kmaxB));
    unsigned tuA = __reduce_max_sync(0xffffffffu, f2ord(tmaxA));
    unsigned tuB = __reduce_max_sync(0xffffffffu, f2ord(tmaxB));

    if (lane == 0) {
        wkt[0][wid] = kuA; wkt[1][wid] = kuB;
        wkt[2][wid] = tuA; wkt[3][wid] = tuB;
    }
    __syncthreads();

    // Masked full-warp REDUX over the 8 per-warp values (identity 0 is safe:
    // all f2ord values are > 0 and kmax counts are >= 1).
    const bool in8 = (lane < NW);
    unsigned kmA = __reduce_max_sync(0xffffffffu, in8 ? wkt[0][lane] : 0u);
    unsigned kmB = __reduce_max_sync(0xffffffffu, in8 ? wkt[1][lane] : 0u);
    unsigned tmA = __reduce_max_sync(0xffffffffu, in8 ? wkt[2][lane] : 0u);
    unsigned tmB = __reduce_max_sync(0xffffffffu, in8 ? wkt[3][lane] : 0u);

    const float tauA = __fdividef(ord2f(tmA) - 1.0f, __uint2float_rn(kmA));
    const float tauB = __fdividef(ord2f(tmB) - 1.0f, __uint2float_rn(kmB));

    // Outputs (streaming stores — evict output first, keep input in L2)
    float4* __restrict__ ya =
        reinterpret_cast<float4*>(y) + (size_t)rowA * ROWF4 + tid * 2;
    float4 oa0, oa1;
    oa0.x = fmaxf(0.0f, zA[0] - tauA); oa0.y = fmaxf(0.0f, zA[1] - tauA);
    oa0.z = fmaxf(0.0f, zA[2] - tauA); oa0.w = fmaxf(0.0f, zA[3] - tauA);
    oa1.x = fmaxf(0.0f, zA[4] - tauA); oa1.y = fmaxf(0.0f, zA[5] - tauA);
    oa1.z = fmaxf(0.0f, zA[6] - tauA); oa1.w = fmaxf(0.0f, zA[7] - tauA);
    __stcs(ya + 0, oa0);
    __stcs(ya + 1, oa1);

    if (hasB) {
        float4* __restrict__ yb = ya + ROWF4;
        float4 ob0, ob1;
        ob0.x = fmaxf(0.0f, zB[0] - tauB); ob0.y = fmaxf(0.0f, zB[1] - tauB);
        ob0.z = fmaxf(0.0f, zB[2] - tauB); ob0.w = fmaxf(0.0f, zB[3] - tauB);
        ob1.x = fmaxf(0.0f, zB[4] - tauB); ob1.y = fmaxf(0.0f, zB[5] - tauB);
        ob1.z = fmaxf(0.0f, zB[6] - tauB); ob1.w = fmaxf(0.0f, zB[7] - tauB);
        __stcs(yb + 0, ob0);
        __stcs(yb + 1, ob1);
    }
}

extern "C" void kernel_launch(void* const* d_in, const int* in_sizes, int n_in,
                              void* d_out, int out_size)
{
    const float* x = (const float*)d_in[0];
    float*       y = (float*)d_out;
    const int rows = out_size / K;             // 8192 for the bench shape
    const int grid = (rows + 1) / 2;           // 4096
    sparsemax_rowwise_kernel<<<grid, THREADS>>>(x, y, rows);
}